// round 16
// baseline (speedup 1.0000x reference)
#include <cuda_runtime.h>
#include <cuda_bf16.h>
#include <cuda_fp16.h>
#include <math.h>
#include <stdint.h>

#define T_TOK 2048
#define HIDN  2048
#define NH    32
#define NKV   4
#define HD    128
#define QKV_N ((NH + 2*NKV)*HD)   /* 5120 */
#define ON    (NH*HD)             /* 4096 */
#define KVW   (NKV*HD)            /* 512 */

// Scratch (static device globals: allocation-free)
__device__ float g_qkv[(size_t)T_TOK * QKV_N];   // ~40 MiB

// fp16 GEMM operands
__device__ __half g_hid_h [(size_t)T_TOK * HIDN];
__device__ __half g_wqkv_h[(size_t)QKV_N * HIDN];
__device__ __half g_wo_h  [(size_t)HIDN * ON];
__device__ __half g_ob    [(size_t)T_TOK * ON];   // flash output (fp16)

// Flash operands: all fp16 single
__device__ __half g_q   [(size_t)T_TOK * ON];    // scaled Q (incl. log2e)
__device__ __half g_k   [(size_t)T_TOK * KVW];
__device__ __half g_vt  [(size_t)NKV * HD * T_TOK];  // V^T fp16

// RoPE table: [T][64] (cos, sin)
__device__ float2 g_rope[(size_t)T_TOK * 64];

// ===========================================================================
// Helpers
// ===========================================================================
__device__ __forceinline__ uint32_t smem_u32(const void* p) {
  uint32_t a;
  asm("{ .reg .u64 t; cvta.to.shared.u64 t, %1; cvt.u32.u64 %0, t; }"
      : "=r"(a) : "l"(p));
  return a;
}

#define LDSM4(r, a)                                                          \
  asm volatile("ldmatrix.sync.aligned.m8n8.x4.shared.b16 {%0,%1,%2,%3}, [%4];" \
    : "=r"((r)[0]), "=r"((r)[1]), "=r"((r)[2]), "=r"((r)[3]) : "r"(a))

#define MMA_F16(c, a, b)                                                     \
  asm volatile("mma.sync.aligned.m16n8k16.row.col.f32.f16.f16.f32 "          \
    "{%0,%1,%2,%3}, {%4,%5,%6,%7}, {%8,%9}, {%0,%1,%2,%3};"                  \
    : "+f"((c)[0]), "+f"((c)[1]), "+f"((c)[2]), "+f"((c)[3])                 \
    : "r"((a)[0]), "r"((a)[1]), "r"((a)[2]), "r"((a)[3]),                    \
      "r"((b)[0]), "r"((b)[1]))

#define CP_ASYNC8(dst, src)                                                  \
  asm volatile("cp.async.ca.shared.global [%0], [%1], 8;" :: "r"(dst), "l"(src))
#define CP_ASYNC16(dst, src)                                                 \
  asm volatile("cp.async.cg.shared.global [%0], [%1], 16;" :: "r"(dst), "l"(src))
#define CP_COMMIT() asm volatile("cp.async.commit_group;" ::: "memory")
#define CP_WAIT2()  asm volatile("cp.async.wait_group 2;" ::: "memory")
#define CP_WAIT1()  asm volatile("cp.async.wait_group 1;" ::: "memory")
#define CP_WAIT0()  asm volatile("cp.async.wait_group 0;" ::: "memory")

// ---------------------------------------------------------------------------
// Convert pass: fp32 -> fp16
// ---------------------------------------------------------------------------
__global__ __launch_bounds__(256) void cvt_f16(
    const float* __restrict__ src, __half* __restrict__ dst, int n4)
{
  const int i = blockIdx.x * 256 + threadIdx.x;
  if (i < n4) {
    float4 v = ((const float4*)src)[i];
    __half2 a = __floats2half2_rn(v.x, v.y);
    __half2 b = __floats2half2_rn(v.z, v.w);
    ((uint2*)dst)[i] = make_uint2(*reinterpret_cast<uint32_t*>(&a),
                                  *reinterpret_cast<uint32_t*>(&b));
  }
}

// ---------------------------------------------------------------------------
// RoPE table: tab[t][i] = (cos, sin) of pos_t * theta^{-i/64}
// ---------------------------------------------------------------------------
__global__ __launch_bounds__(256) void rope_table(
    const int* __restrict__ positions, float2* __restrict__ tab)
{
  const int idx = blockIdx.x * 256 + threadIdx.x;   // T*64 total
  const int t = idx >> 6, i = idx & 63;
  const float inv = exp2f(-(float)i * (19.931568569324174f / 64.0f));
  float s, c;
  sincosf((float)positions[t] * inv, &s, &c);
  tab[idx] = make_float2(c, s);
}

// ===========================================================================
// fp16 single-term HMMA GEMM (unchanged from R12-R15 passing versions)
// ===========================================================================
#define KC 32
#define KP 40
#define TILE_E (128 * KP)
#define STAGE_E (2 * TILE_E)
#define NSTAGE 4
#define GEMM_SMEM (NSTAGE * STAGE_E * 2)

__global__ __launch_bounds__(512) void gemm_mma(
    const __half* __restrict__ A, const __half* __restrict__ B,
    float* __restrict__ C, int M, int N, int K)
{
  extern __shared__ __half sm[];
  const uint32_t sbase = smem_u32(sm);
  const int tid  = threadIdx.x;
  const int lane = tid & 31;
  const int w    = tid >> 5;
  const int wm   = w & 3;
  const int wn   = w >> 2;
  const int bm   = blockIdx.y, bn = blockIdx.x;

  const __half* tb[2] = { A + (size_t)bm * 128 * K, B + (size_t)bn * 128 * K };

  const int mi  = lane >> 3, li = lane & 7;
  const int a_r = ((mi & 1) << 3) + li;
  const int a_k = (mi >> 1) << 3;
  const int b_r = ((mi >> 1) << 3) + li;
  const int b_k = (mi & 1) << 3;

  float acc[2][4][4];
  #pragma unroll
  for (int mt = 0; mt < 2; ++mt)
    #pragma unroll
    for (int nt = 0; nt < 4; ++nt)
      #pragma unroll
      for (int q = 0; q < 4; ++q) acc[mt][nt][q] = 0.f;

  auto LOAD = [&](int ch) {
    const int s = ch & (NSTAGE - 1);
    const uint32_t st = sbase + (uint32_t)(s * STAGE_E * 2);
    const int kb = ch * KC;
    #pragma unroll
    for (int tile = 0; tile < 2; ++tile) {
      #pragma unroll
      for (int j = 0; j < 2; ++j) {
        const int c   = tid + j * 512;
        const int row = c >> 3;
        const int k8  = (c & 7) << 2;
        const __half* src = tb[tile] + (size_t)row * K + kb + k8;
        const uint32_t dst = st + (uint32_t)((tile * TILE_E + row * KP + k8) << 1);
        CP_ASYNC8(dst, src);
      }
    }
    CP_COMMIT();
  };

  auto COMP = [&](int ch) {
    const uint32_t base = sbase + (uint32_t)((ch & (NSTAGE - 1)) * STAGE_E * 2);
    #pragma unroll
    for (int ks = 0; ks < 2; ++ks) {
      uint32_t af[2][4], bf[2][4];
      #pragma unroll
      for (int mt = 0; mt < 2; ++mt) {
        uint32_t ad = base + (uint32_t)(((wm * 32 + mt * 16 + a_r) * KP +
                                         ks * 16 + a_k) << 1);
        LDSM4(af[mt], ad);
      }
      #pragma unroll
      for (int np = 0; np < 2; ++np) {
        uint32_t bd = base + (uint32_t)((TILE_E + (wn * 32 + np * 16 + b_r) * KP +
                                         ks * 16 + b_k) << 1);
        LDSM4(bf[np], bd);
      }
      #pragma unroll
      for (int mt = 0; mt < 2; ++mt)
        #pragma unroll
        for (int nt = 0; nt < 4; ++nt)
          MMA_F16(acc[mt][nt], af[mt], (&bf[nt >> 1][(nt & 1) * 2]));
    }
  };

  const int NC = K / KC;
  LOAD(0); LOAD(1); LOAD(2);
  for (int ch = 0; ch < NC; ++ch) {
    CP_WAIT2();
    __syncthreads();
    if (ch + 3 < NC) LOAD(ch + 3);
    COMP(ch);
  }

  #pragma unroll
  for (int mt = 0; mt < 2; ++mt) {
    const int r0 = bm * 128 + wm * 32 + mt * 16 + (lane >> 2);
    #pragma unroll
    for (int nt = 0; nt < 4; ++nt) {
      const int c0 = bn * 128 + wn * 32 + nt * 8 + ((lane & 3) << 1);
      *(float2*)&C[(size_t)r0 * N + c0] =
          make_float2(acc[mt][nt][0], acc[mt][nt][1]);
      *(float2*)&C[(size_t)(r0 + 8) * N + c0] =
          make_float2(acc[mt][nt][2], acc[mt][nt][3]);
    }
  }
}

// ---------------------------------------------------------------------------
// Per-head RMSNorm + NeoX RoPE (table-driven) -> Q fp16 (scaled·log2e), K fp16
// ---------------------------------------------------------------------------
__global__ __launch_bounds__(128) void norm_rope(
    const float* __restrict__ qkv, const float2* __restrict__ rope,
    const float* __restrict__ qw, const float* __restrict__ kw,
    __half* __restrict__ Qf, __half* __restrict__ Kf)
{
  const int t  = blockIdx.x;
  const int hh = blockIdx.y;
  const int d  = threadIdx.x;
  const float* base = qkv + (size_t)t * QKV_N +
                      (hh < NH ? hh * HD : NH * HD + (hh - NH) * HD);
  const float* w = (hh < NH) ? qw : kw;

  float x  = base[d];
  float ss = x * x;
  #pragma unroll
  for (int off = 16; off > 0; off >>= 1)
    ss += __shfl_xor_sync(0xffffffffu, ss, off);
  __shared__ float red[4];
  __shared__ float ybuf[HD];
  if ((d & 31) == 0) red[d >> 5] = ss;
  __syncthreads();
  float tot = red[0] + red[1] + red[2] + red[3];
  float y = x * rsqrtf(tot * (1.0f / HD) + 1e-6f) * w[d];
  ybuf[d] = y;
  __syncthreads();

  const float2 cs = rope[t * 64 + (d & 63)];
  float out;
  if (d < 64) out = y * cs.x - ybuf[d + 64] * cs.y;
  else        out = ybuf[d - 64] * cs.y + y * cs.x;

  if (hh < NH) {
    // pre-scale Q by 1/sqrt(128) * log2(e) (softmax uses exp2)
    const float v = out * (0.08838834764831845f * 1.4426950408889634f);
    Qf[(size_t)t * ON + hh * HD + d] = __float2half_rn(v);
  } else {
    Kf[(size_t)t * KVW + (hh - NH) * HD + d] = __float2half_rn(out);
  }
}

// ---------------------------------------------------------------------------
// V transpose: qkv V slice -> VT[kvh][hd][t] fp16
// ---------------------------------------------------------------------------
__global__ __launch_bounds__(256) void vtrans(
    const float* __restrict__ qkv, __half* __restrict__ Vt)
{
  __shared__ float vs[HD][65];
  const int tid = threadIdx.x;
  const int t0  = blockIdx.x * 64;
  const int kvh = blockIdx.y;

  #pragma unroll
  for (int it = 0; it < 8; ++it) {
    const int idx = tid + it * 256;
    const int r = idx >> 5, c = (idx & 31) << 2;
    float4 v = *(const float4*)(qkv + (size_t)(t0 + r) * QKV_N +
                                (NH + NKV) * HD + kvh * HD + c);
    vs[c+0][r] = v.x; vs[c+1][r] = v.y; vs[c+2][r] = v.z; vs[c+3][r] = v.w;
  }
  __syncthreads();

  #pragma unroll
  for (int it = 0; it < 8; ++it) {
    const int idx = tid + it * 256;
    const int hd = idx >> 4, tg = (idx & 15) << 2;
    __half2 a = __floats2half2_rn(vs[hd][tg],   vs[hd][tg+1]);
    __half2 b = __floats2half2_rn(vs[hd][tg+2], vs[hd][tg+3]);
    const size_t o = ((size_t)kvh * HD + hd) * T_TOK + t0 + tg;
    *(uint2*)(Vt + o) = make_uint2(*reinterpret_cast<uint32_t*>(&a),
                                   *reinterpret_cast<uint32_t*>(&b));
  }
}

// ===========================================================================
// Flash attention: fp16 1-term S and PV, exp2 softmax, 2 CTAs/SM.
// CTA: 128 q-rows x 1 head, 8 warps x 16 q-rows. K-tile 64. Causal, GQA.
// ===========================================================================
#define ABM 128
#define ABN 64
#define QP  136
#define VTP 72
#define SST 17408                 /* stage area start (elems) */
#define STG 17920                 /* per stage: K (8704) + V (9216) */
#define FV  8704
#define FLASH_SMEM ((SST + 2 * STG) * 2)   /* 106496 B */

__global__ __launch_bounds__(256, 2) void flash_mma(
    const __half* __restrict__ Qf, const __half* __restrict__ Kf,
    const __half* __restrict__ Vt, __half* __restrict__ ob)
{
  extern __shared__ __half sb[];
  const uint32_t sbase = smem_u32(sb);
  const int tid  = threadIdx.x;
  const int lane = tid & 31;
  const int w    = tid >> 5;
  const int qblk = (int)gridDim.x - 1 - (int)blockIdx.x;   // LPT: big first
  const int q0   = qblk * ABM;
  const int h    = blockIdx.y;
  const int kvh  = h >> 3;

  const int mi  = lane >> 3, li = lane & 7;
  const int a_r = ((mi & 1) << 3) + li;
  const int a_k = (mi >> 1) << 3;
  const int b_r = ((mi >> 1) << 3) + li;
  const int b_k = (mi & 1) << 3;

  // ---- Q tile via cp.async: 128 rows x 16 chunks ----
  {
    #pragma unroll
    for (int it = 0; it < 8; ++it) {
      const int c   = tid + it * 256;     // 0..2047
      const int row = c >> 4, col = (c & 15) << 3;
      const __half* src = Qf + (size_t)(q0 + row) * ON + h * HD + col;
      const uint32_t dst = sbase + (uint32_t)((row * QP + col) << 1);
      CP_ASYNC16(dst, src);
    }
  }

  auto LOADKV = [&](int kt) {
    const int s  = kt & 1;
    const int k0 = kt * ABN;
    const uint32_t stb = sbase + (uint32_t)((SST + s * STG) << 1);
    #pragma unroll
    for (int it = 0; it < 8; ++it) {
      const int c    = tid + it * 256;     // 0..2047
      const int tile = c >> 10;            // 0=K 1=V
      const int cc   = c & 1023;
      if (tile == 0) {                     // K: 64 rows x 16 chunks
        const int row = cc >> 4, col = (cc & 15) << 3;
        const __half* src = Kf + (size_t)(k0 + row) * KVW + kvh * HD + col;
        CP_ASYNC16(stb + (uint32_t)((row * QP + col) << 1), src);
      } else {                             // V: 128 rows x 8 chunks
        const int row = cc >> 3, col = (cc & 7) << 3;
        const __half* src = Vt + ((size_t)kvh * HD + row) * T_TOK + k0 + col;
        CP_ASYNC16(stb + (uint32_t)((FV + row * VTP + col) << 1), src);
      }
    }
    CP_COMMIT();
  };

  float oacc[16][4];
  #pragma unroll
  for (int nt = 0; nt < 16; ++nt)
    #pragma unroll
    for (int q = 0; q < 4; ++q) oacc[nt][q] = 0.f;
  float mA = -1e30f, mB = -1e30f, lA = 0.f, lB = 0.f;

  const int ktmax = q0 / ABN + 1;
  LOADKV(0);
  if (ktmax >= 1) LOADKV(1);

  for (int kt = 0; kt <= ktmax; ++kt) {
    const int k0 = kt * ABN;
    if (kt < ktmax) { CP_WAIT1(); } else { CP_WAIT0(); }
    __syncthreads();

    const uint32_t stb = sbase + (uint32_t)((SST + (kt & 1) * STG) << 1);

    // ---- S = Q @ K^T (fp16 1-term; S is pre-scaled by log2e) ----
    float sacc[8][4];
    #pragma unroll
    for (int nt = 0; nt < 8; ++nt)
      #pragma unroll
      for (int q = 0; q < 4; ++q) sacc[nt][q] = 0.f;

    #pragma unroll
    for (int ks = 0; ks < 8; ++ks) {
      uint32_t qf[4], kf[4][4];
      const uint32_t qa = sbase + (uint32_t)(((w * 16 + a_r) * QP +
                                             ks * 16 + a_k) << 1);
      LDSM4(qf, qa);
      #pragma unroll
      for (int np = 0; np < 4; ++np) {
        const uint32_t ka = stb + (uint32_t)(((np * 16 + b_r) * QP +
                                              ks * 16 + b_k) << 1);
        LDSM4(kf[np], ka);
      }
      #pragma unroll
      for (int nt = 0; nt < 8; ++nt)
        MMA_F16(sacc[nt], qf, (&kf[nt >> 1][(nt & 1) * 2]));
    }

    const int qrA = q0 + w * 16 + (lane >> 2);
    const int qrB = qrA + 8;
    if (k0 + ABN - 1 > q0) {   // causal mask
      #pragma unroll
      for (int nt = 0; nt < 8; ++nt) {
        const int kc = k0 + nt * 8 + ((lane & 3) << 1);
        if (kc     > qrA) sacc[nt][0] = -1e30f;
        if (kc + 1 > qrA) sacc[nt][1] = -1e30f;
        if (kc     > qrB) sacc[nt][2] = -1e30f;
        if (kc + 1 > qrB) sacc[nt][3] = -1e30f;
      }
    }

    // ---- online softmax (base-2) ----
    float mxA = -1e30f, mxB = -1e30f;
    #pragma unroll
    for (int nt = 0; nt < 8; ++nt) {
      mxA = fmaxf(mxA, fmaxf(sacc[nt][0], sacc[nt][1]));
      mxB = fmaxf(mxB, fmaxf(sacc[nt][2], sacc[nt][3]));
    }
    mxA = fmaxf(mxA, __shfl_xor_sync(0xffffffffu, mxA, 1));
    mxA = fmaxf(mxA, __shfl_xor_sync(0xffffffffu, mxA, 2));
    mxB = fmaxf(mxB, __shfl_xor_sync(0xffffffffu, mxB, 1));
    mxB = fmaxf(mxB, __shfl_xor_sync(0xffffffffu, mxB, 2));
    const float mnA = fmaxf(mA, mxA), mnB = fmaxf(mB, mxB);
    const float cA = exp2f(mA - mnA), cB = exp2f(mB - mnB);
    mA = mnA; mB = mnB;

    float rsA = 0.f, rsB = 0.f;
    #pragma unroll
    for (int nt = 0; nt < 8; ++nt) {
      sacc[nt][0] = exp2f(sacc[nt][0] - mnA);
      sacc[nt][1] = exp2f(sacc[nt][1] - mnA);
      sacc[nt][2] = exp2f(sacc[nt][2] - mnB);
      sacc[nt][3] = exp2f(sacc[nt][3] - mnB);
      rsA += sacc[nt][0] + sacc[nt][1];
      rsB += sacc[nt][2] + sacc[nt][3];
    }
    rsA += __shfl_xor_sync(0xffffffffu, rsA, 1);
    rsA += __shfl_xor_sync(0xffffffffu, rsA, 2);
    rsB += __shfl_xor_sync(0xffffffffu, rsB, 1);
    rsB += __shfl_xor_sync(0xffffffffu, rsB, 2);
    lA = lA * cA + rsA;
    lB = lB * cB + rsB;
    #pragma unroll
    for (int nt = 0; nt < 16; ++nt) {
      oacc[nt][0] *= cA; oacc[nt][1] *= cA;
      oacc[nt][2] *= cB; oacc[nt][3] *= cB;
    }

    // ---- O += P @ V (fp16 1-term) ----
    #pragma unroll
    for (int kk = 0; kk < 4; ++kk) {
      uint32_t ph[4];
      __half2 p0 = __floats2half2_rn(sacc[2*kk][0],   sacc[2*kk][1]);
      __half2 p1 = __floats2half2_rn(sacc[2*kk][2],   sacc[2*kk][3]);
      __half2 p2 = __floats2half2_rn(sacc[2*kk+1][0], sacc[2*kk+1][1]);
      __half2 p3 = __floats2half2_rn(sacc[2*kk+1][2], sacc[2*kk+1][3]);
      ph[0] = *reinterpret_cast<uint32_t*>(&p0);
      ph[1] = *reinterpret_cast<uint32_t*>(&p1);
      ph[2] = *reinterpret_cast<uint32_t*>(&p2);
      ph[3] = *reinterpret_cast<uint32_t*>(&p3);
      #pragma unroll
      for (int np = 0; np < 8; ++np) {
        uint32_t vf[4];
        const uint32_t va = stb + (uint32_t)((FV + (np * 16 + b_r) * VTP +
                                              kk * 16 + b_k) << 1);
        LDSM4(vf, va);
        MMA_F16(oacc[2*np],   ph, (&vf[0]));
        MMA_F16(oacc[2*np+1], ph, (&vf[2]));
      }
    }

    __syncthreads();
    if (kt + 2 <= ktmax) LOADKV(kt + 2);
  }

  // ---- epilogue: write fp16 (GEMM2 A operand) ----
  const float invA = 1.0f / lA, invB = 1.0f / lB;
  const int rowA = q0 + w * 16 + (lane >> 2);
  #pragma unroll
  for (int nt = 0; nt < 16; ++nt) {
    const int c0 = h * HD + nt * 8 + ((lane & 3) << 1);
    __half2 pa = __floats2half2_rn(oacc[nt][0] * invA, oacc[nt][1] * invA);
    __half2 pb = __floats2half2_rn(oacc[nt][2] * invB, oacc[nt][3] * invB);
    *(__half2*)&ob[(size_t)rowA * ON + c0]       = pa;
    *(__half2*)&ob[(size_t)(rowA + 8) * ON + c0] = pb;
  }
}

// ---------------------------------------------------------------------------
extern "C" void kernel_launch(void* const* d_in, const int* in_sizes, int n_in,
                              void* d_out, int out_size)
{
  (void)in_sizes; (void)n_in; (void)out_size;
  const int*   positions = (const int*)  d_in[0];
  const float* hidden    = (const float*)d_in[1];
  const float* w_qkv     = (const float*)d_in[2];
  const float* w_o       = (const float*)d_in[3];
  const float* qw        = (const float*)d_in[4];
  const float* kw        = (const float*)d_in[5];
  float* out = (float*)d_out;

  float* qkv;
  cudaGetSymbolAddress((void**)&qkv, g_qkv);
  __half *hid_h, *wqkv_h, *wo_h, *ob, *vt, *qf, *kf;
  float2* rope;
  cudaGetSymbolAddress((void**)&hid_h,  g_hid_h);
  cudaGetSymbolAddress((void**)&wqkv_h, g_wqkv_h);
  cudaGetSymbolAddress((void**)&wo_h,   g_wo_h);
  cudaGetSymbolAddress((void**)&ob,     g_ob);
  cudaGetSymbolAddress((void**)&vt,     g_vt);
  cudaGetSymbolAddress((void**)&qf,     g_q);
  cudaGetSymbolAddress((void**)&kf,     g_k);
  cudaGetSymbolAddress((void**)&rope,   g_rope);

  cudaFuncSetAttribute(gemm_mma, cudaFuncAttributeMaxDynamicSharedMemorySize,
                       GEMM_SMEM);
  cudaFuncSetAttribute(flash_mma, cudaFuncAttributeMaxDynamicSharedMemorySize,
                       FLASH_SMEM);

  // 0) fp32 -> fp16 operand converts for GEMM1 + rope table
  {
    int n4 = T_TOK * HIDN / 4;
    cvt_f16<<<(n4 + 255) / 256, 256>>>(hidden, hid_h, n4);
    n4 = QKV_N * HIDN / 4;
    cvt_f16<<<(n4 + 255) / 256, 256>>>(w_qkv, wqkv_h, n4);
    rope_table<<<(T_TOK * 64) / 256, 256>>>(positions, rope);
  }

  // 1) QKV projection (fp16 single-term HMMA)
  gemm_mma<<<dim3(QKV_N/128, T_TOK/128), 512, GEMM_SMEM>>>(
      hid_h, wqkv_h, qkv, T_TOK, QKV_N, HIDN);

  // 2) RMSNorm + RoPE (table) -> Q/K fp16 ; V transpose (fp16)
  norm_rope<<<dim3(T_TOK, NH + NKV), 128>>>(qkv, rope, qw, kw, qf, kf);
  vtrans<<<dim3(T_TOK/64, NKV), 256>>>(qkv, vt);

  // 3) Causal GQA flash attention (fp16, exp2 softmax, 2 CTAs/SM, LPT)
  flash_mma<<<dim3(T_TOK/ABM, NH), 256, FLASH_SMEM>>>(qf, kf, vt, ob);

  // 4) fp32 -> fp16 convert for w_o
  {
    int n4 = HIDN * ON / 4;
    cvt_f16<<<(n4 + 255) / 256, 256>>>(w_o, wo_h, n4);
  }

  // 5) Output projection (fp16 single-term HMMA)
  gemm_mma<<<dim3(HIDN/128, T_TOK/128), 512, GEMM_SMEM>>>(
      ob, wo_h, out, T_TOK, HIDN, ON);
}

// round 17
// speedup vs baseline: 1.0114x; 1.0114x over previous
#include <cuda_runtime.h>
#include <cuda_bf16.h>
#include <cuda_fp16.h>
#include <math.h>
#include <stdint.h>

#define T_TOK 2048
#define HIDN  2048
#define NH    32
#define NKV   4
#define HD    128
#define QKV_N ((NH + 2*NKV)*HD)   /* 5120 */
#define ON    (NH*HD)             /* 4096 */
#define KVW   (NKV*HD)            /* 512 */

// Scratch (static device globals: allocation-free)
__device__ float g_qkv[(size_t)T_TOK * QKV_N];   // ~40 MiB

// fp16 GEMM operands
__device__ __half g_hid_h [(size_t)T_TOK * HIDN];
__device__ __half g_wqkv_h[(size_t)QKV_N * HIDN];
__device__ __half g_wo_h  [(size_t)HIDN * ON];
__device__ __half g_ob    [(size_t)T_TOK * ON];   // flash output (fp16)

// Flash operands: all fp16 single
__device__ __half g_q   [(size_t)T_TOK * ON];    // scaled Q (incl. log2e)
__device__ __half g_k   [(size_t)T_TOK * KVW];
__device__ __half g_vt  [(size_t)NKV * HD * T_TOK];  // V^T fp16

// RoPE table: [T][64] (cos, sin)
__device__ float2 g_rope[(size_t)T_TOK * 64];

// ===========================================================================
// Helpers
// ===========================================================================
__device__ __forceinline__ uint32_t smem_u32(const void* p) {
  uint32_t a;
  asm("{ .reg .u64 t; cvta.to.shared.u64 t, %1; cvt.u32.u64 %0, t; }"
      : "=r"(a) : "l"(p));
  return a;
}

#define LDSM4(r, a)                                                          \
  asm volatile("ldmatrix.sync.aligned.m8n8.x4.shared.b16 {%0,%1,%2,%3}, [%4];" \
    : "=r"((r)[0]), "=r"((r)[1]), "=r"((r)[2]), "=r"((r)[3]) : "r"(a))

#define MMA_F16(c, a, b)                                                     \
  asm volatile("mma.sync.aligned.m16n8k16.row.col.f32.f16.f16.f32 "          \
    "{%0,%1,%2,%3}, {%4,%5,%6,%7}, {%8,%9}, {%0,%1,%2,%3};"                  \
    : "+f"((c)[0]), "+f"((c)[1]), "+f"((c)[2]), "+f"((c)[3])                 \
    : "r"((a)[0]), "r"((a)[1]), "r"((a)[2]), "r"((a)[3]),                    \
      "r"((b)[0]), "r"((b)[1]))

#define CP_ASYNC8(dst, src)                                                  \
  asm volatile("cp.async.ca.shared.global [%0], [%1], 8;" :: "r"(dst), "l"(src))
#define CP_ASYNC16(dst, src)                                                 \
  asm volatile("cp.async.cg.shared.global [%0], [%1], 16;" :: "r"(dst), "l"(src))
#define CP_COMMIT() asm volatile("cp.async.commit_group;" ::: "memory")
#define CP_WAIT2()  asm volatile("cp.async.wait_group 2;" ::: "memory")
#define CP_WAIT1()  asm volatile("cp.async.wait_group 1;" ::: "memory")
#define CP_WAIT0()  asm volatile("cp.async.wait_group 0;" ::: "memory")

// ---------------------------------------------------------------------------
// Convert pass: fp32 -> fp16
// ---------------------------------------------------------------------------
__global__ __launch_bounds__(256) void cvt_f16(
    const float* __restrict__ src, __half* __restrict__ dst, int n4)
{
  const int i = blockIdx.x * 256 + threadIdx.x;
  if (i < n4) {
    float4 v = ((const float4*)src)[i];
    __half2 a = __floats2half2_rn(v.x, v.y);
    __half2 b = __floats2half2_rn(v.z, v.w);
    ((uint2*)dst)[i] = make_uint2(*reinterpret_cast<uint32_t*>(&a),
                                  *reinterpret_cast<uint32_t*>(&b));
  }
}

// ---------------------------------------------------------------------------
// RoPE table: tab[t][i] = (cos, sin) of pos_t * theta^{-i/64}
// ---------------------------------------------------------------------------
__global__ __launch_bounds__(256) void rope_table(
    const int* __restrict__ positions, float2* __restrict__ tab)
{
  const int idx = blockIdx.x * 256 + threadIdx.x;   // T*64 total
  const int t = idx >> 6, i = idx & 63;
  const float inv = exp2f(-(float)i * (19.931568569324174f / 64.0f));
  float s, c;
  sincosf((float)positions[t] * inv, &s, &c);
  tab[idx] = make_float2(c, s);
}

// ===========================================================================
// fp16 single-term HMMA GEMM (unchanged from R12-R16 passing versions)
// ===========================================================================
#define KC 32
#define KP 40
#define TILE_E (128 * KP)
#define STAGE_E (2 * TILE_E)
#define NSTAGE 4
#define GEMM_SMEM (NSTAGE * STAGE_E * 2)

__global__ __launch_bounds__(512) void gemm_mma(
    const __half* __restrict__ A, const __half* __restrict__ B,
    float* __restrict__ C, int M, int N, int K)
{
  extern __shared__ __half sm[];
  const uint32_t sbase = smem_u32(sm);
  const int tid  = threadIdx.x;
  const int lane = tid & 31;
  const int w    = tid >> 5;
  const int wm   = w & 3;
  const int wn   = w >> 2;
  const int bm   = blockIdx.y, bn = blockIdx.x;

  const __half* tb[2] = { A + (size_t)bm * 128 * K, B + (size_t)bn * 128 * K };

  const int mi  = lane >> 3, li = lane & 7;
  const int a_r = ((mi & 1) << 3) + li;
  const int a_k = (mi >> 1) << 3;
  const int b_r = ((mi >> 1) << 3) + li;
  const int b_k = (mi & 1) << 3;

  float acc[2][4][4];
  #pragma unroll
  for (int mt = 0; mt < 2; ++mt)
    #pragma unroll
    for (int nt = 0; nt < 4; ++nt)
      #pragma unroll
      for (int q = 0; q < 4; ++q) acc[mt][nt][q] = 0.f;

  auto LOAD = [&](int ch) {
    const int s = ch & (NSTAGE - 1);
    const uint32_t st = sbase + (uint32_t)(s * STAGE_E * 2);
    const int kb = ch * KC;
    #pragma unroll
    for (int tile = 0; tile < 2; ++tile) {
      #pragma unroll
      for (int j = 0; j < 2; ++j) {
        const int c   = tid + j * 512;
        const int row = c >> 3;
        const int k8  = (c & 7) << 2;
        const __half* src = tb[tile] + (size_t)row * K + kb + k8;
        const uint32_t dst = st + (uint32_t)((tile * TILE_E + row * KP + k8) << 1);
        CP_ASYNC8(dst, src);
      }
    }
    CP_COMMIT();
  };

  auto COMP = [&](int ch) {
    const uint32_t base = sbase + (uint32_t)((ch & (NSTAGE - 1)) * STAGE_E * 2);
    #pragma unroll
    for (int ks = 0; ks < 2; ++ks) {
      uint32_t af[2][4], bf[2][4];
      #pragma unroll
      for (int mt = 0; mt < 2; ++mt) {
        uint32_t ad = base + (uint32_t)(((wm * 32 + mt * 16 + a_r) * KP +
                                         ks * 16 + a_k) << 1);
        LDSM4(af[mt], ad);
      }
      #pragma unroll
      for (int np = 0; np < 2; ++np) {
        uint32_t bd = base + (uint32_t)((TILE_E + (wn * 32 + np * 16 + b_r) * KP +
                                         ks * 16 + b_k) << 1);
        LDSM4(bf[np], bd);
      }
      #pragma unroll
      for (int mt = 0; mt < 2; ++mt)
        #pragma unroll
        for (int nt = 0; nt < 4; ++nt)
          MMA_F16(acc[mt][nt], af[mt], (&bf[nt >> 1][(nt & 1) * 2]));
    }
  };

  const int NC = K / KC;
  LOAD(0); LOAD(1); LOAD(2);
  for (int ch = 0; ch < NC; ++ch) {
    CP_WAIT2();
    __syncthreads();
    if (ch + 3 < NC) LOAD(ch + 3);
    COMP(ch);
  }

  #pragma unroll
  for (int mt = 0; mt < 2; ++mt) {
    const int r0 = bm * 128 + wm * 32 + mt * 16 + (lane >> 2);
    #pragma unroll
    for (int nt = 0; nt < 4; ++nt) {
      const int c0 = bn * 128 + wn * 32 + nt * 8 + ((lane & 3) << 1);
      *(float2*)&C[(size_t)r0 * N + c0] =
          make_float2(acc[mt][nt][0], acc[mt][nt][1]);
      *(float2*)&C[(size_t)(r0 + 8) * N + c0] =
          make_float2(acc[mt][nt][2], acc[mt][nt][3]);
    }
  }
}

// ---------------------------------------------------------------------------
// Per-head RMSNorm + NeoX RoPE (table-driven) -> Q fp16 (scaled·log2e), K fp16
// ---------------------------------------------------------------------------
__global__ __launch_bounds__(128) void norm_rope(
    const float* __restrict__ qkv, const float2* __restrict__ rope,
    const float* __restrict__ qw, const float* __restrict__ kw,
    __half* __restrict__ Qf, __half* __restrict__ Kf)
{
  const int t  = blockIdx.x;
  const int hh = blockIdx.y;
  const int d  = threadIdx.x;
  const float* base = qkv + (size_t)t * QKV_N +
                      (hh < NH ? hh * HD : NH * HD + (hh - NH) * HD);
  const float* w = (hh < NH) ? qw : kw;

  float x  = base[d];
  float ss = x * x;
  #pragma unroll
  for (int off = 16; off > 0; off >>= 1)
    ss += __shfl_xor_sync(0xffffffffu, ss, off);
  __shared__ float red[4];
  __shared__ float ybuf[HD];
  if ((d & 31) == 0) red[d >> 5] = ss;
  __syncthreads();
  float tot = red[0] + red[1] + red[2] + red[3];
  float y = x * rsqrtf(tot * (1.0f / HD) + 1e-6f) * w[d];
  ybuf[d] = y;
  __syncthreads();

  const float2 cs = rope[t * 64 + (d & 63)];
  float out;
  if (d < 64) out = y * cs.x - ybuf[d + 64] * cs.y;
  else        out = ybuf[d - 64] * cs.y + y * cs.x;

  if (hh < NH) {
    // pre-scale Q by 1/sqrt(128) * log2(e) (softmax uses exp2)
    const float v = out * (0.08838834764831845f * 1.4426950408889634f);
    Qf[(size_t)t * ON + hh * HD + d] = __float2half_rn(v);
  } else {
    Kf[(size_t)t * KVW + (hh - NH) * HD + d] = __float2half_rn(out);
  }
}

// ---------------------------------------------------------------------------
// V transpose: qkv V slice -> VT[kvh][hd][t] fp16
// ---------------------------------------------------------------------------
__global__ __launch_bounds__(256) void vtrans(
    const float* __restrict__ qkv, __half* __restrict__ Vt)
{
  __shared__ float vs[HD][65];
  const int tid = threadIdx.x;
  const int t0  = blockIdx.x * 64;
  const int kvh = blockIdx.y;

  #pragma unroll
  for (int it = 0; it < 8; ++it) {
    const int idx = tid + it * 256;
    const int r = idx >> 5, c = (idx & 31) << 2;
    float4 v = *(const float4*)(qkv + (size_t)(t0 + r) * QKV_N +
                                (NH + NKV) * HD + kvh * HD + c);
    vs[c+0][r] = v.x; vs[c+1][r] = v.y; vs[c+2][r] = v.z; vs[c+3][r] = v.w;
  }
  __syncthreads();

  #pragma unroll
  for (int it = 0; it < 8; ++it) {
    const int idx = tid + it * 256;
    const int hd = idx >> 4, tg = (idx & 15) << 2;
    __half2 a = __floats2half2_rn(vs[hd][tg],   vs[hd][tg+1]);
    __half2 b = __floats2half2_rn(vs[hd][tg+2], vs[hd][tg+3]);
    const size_t o = ((size_t)kvh * HD + hd) * T_TOK + t0 + tg;
    *(uint2*)(Vt + o) = make_uint2(*reinterpret_cast<uint32_t*>(&a),
                                   *reinterpret_cast<uint32_t*>(&b));
  }
}

// ===========================================================================
// Flash attention: fp16 1-term S and PV, exp2 softmax, 1 CTA/SM (reverted).
// CTA: 128 q-rows x 1 head, 8 warps x 16 q-rows. K-tile 64. Causal, GQA.
// ===========================================================================
#define ABM 128
#define ABN 64
#define QP  136
#define VTP 72
#define SST 17408                 /* stage area start (elems) */
#define STG 17920                 /* per stage: K (8704) + V (9216) */
#define FV  8704
#define FLASH_SMEM ((SST + 2 * STG) * 2)   /* 106496 B */

__global__ __launch_bounds__(256, 1) void flash_mma(
    const __half* __restrict__ Qf, const __half* __restrict__ Kf,
    const __half* __restrict__ Vt, __half* __restrict__ ob)
{
  extern __shared__ __half sb[];
  const uint32_t sbase = smem_u32(sb);
  const int tid  = threadIdx.x;
  const int lane = tid & 31;
  const int w    = tid >> 5;
  const int qblk = (int)gridDim.x - 1 - (int)blockIdx.x;   // LPT: big first
  const int q0   = qblk * ABM;
  const int h    = blockIdx.y;
  const int kvh  = h >> 3;

  const int mi  = lane >> 3, li = lane & 7;
  const int a_r = ((mi & 1) << 3) + li;
  const int a_k = (mi >> 1) << 3;
  const int b_r = ((mi >> 1) << 3) + li;
  const int b_k = (mi & 1) << 3;

  // ---- Q tile via cp.async: 128 rows x 16 chunks ----
  {
    #pragma unroll
    for (int it = 0; it < 8; ++it) {
      const int c   = tid + it * 256;     // 0..2047
      const int row = c >> 4, col = (c & 15) << 3;
      const __half* src = Qf + (size_t)(q0 + row) * ON + h * HD + col;
      const uint32_t dst = sbase + (uint32_t)((row * QP + col) << 1);
      CP_ASYNC16(dst, src);
    }
  }

  auto LOADKV = [&](int kt) {
    const int s  = kt & 1;
    const int k0 = kt * ABN;
    const uint32_t stb = sbase + (uint32_t)((SST + s * STG) << 1);
    #pragma unroll
    for (int it = 0; it < 8; ++it) {
      const int c    = tid + it * 256;     // 0..2047
      const int tile = c >> 10;            // 0=K 1=V
      const int cc   = c & 1023;
      if (tile == 0) {                     // K: 64 rows x 16 chunks
        const int row = cc >> 4, col = (cc & 15) << 3;
        const __half* src = Kf + (size_t)(k0 + row) * KVW + kvh * HD + col;
        CP_ASYNC16(stb + (uint32_t)((row * QP + col) << 1), src);
      } else {                             // V: 128 rows x 8 chunks
        const int row = cc >> 3, col = (cc & 7) << 3;
        const __half* src = Vt + ((size_t)kvh * HD + row) * T_TOK + k0 + col;
        CP_ASYNC16(stb + (uint32_t)((FV + row * VTP + col) << 1), src);
      }
    }
    CP_COMMIT();
  };

  float oacc[16][4];
  #pragma unroll
  for (int nt = 0; nt < 16; ++nt)
    #pragma unroll
    for (int q = 0; q < 4; ++q) oacc[nt][q] = 0.f;
  float mA = -1e30f, mB = -1e30f, lA = 0.f, lB = 0.f;

  const int ktmax = q0 / ABN + 1;
  LOADKV(0);
  if (ktmax >= 1) LOADKV(1);

  for (int kt = 0; kt <= ktmax; ++kt) {
    const int k0 = kt * ABN;
    if (kt < ktmax) { CP_WAIT1(); } else { CP_WAIT0(); }
    __syncthreads();

    const uint32_t stb = sbase + (uint32_t)((SST + (kt & 1) * STG) << 1);

    // ---- S = Q @ K^T (fp16 1-term; S pre-scaled by log2e) ----
    float sacc[8][4];
    #pragma unroll
    for (int nt = 0; nt < 8; ++nt)
      #pragma unroll
      for (int q = 0; q < 4; ++q) sacc[nt][q] = 0.f;

    #pragma unroll
    for (int ks = 0; ks < 8; ++ks) {
      uint32_t qf[4], kf[4][4];
      const uint32_t qa = sbase + (uint32_t)(((w * 16 + a_r) * QP +
                                             ks * 16 + a_k) << 1);
      LDSM4(qf, qa);
      #pragma unroll
      for (int np = 0; np < 4; ++np) {
        const uint32_t ka = stb + (uint32_t)(((np * 16 + b_r) * QP +
                                              ks * 16 + b_k) << 1);
        LDSM4(kf[np], ka);
      }
      #pragma unroll
      for (int nt = 0; nt < 8; ++nt)
        MMA_F16(sacc[nt], qf, (&kf[nt >> 1][(nt & 1) * 2]));
    }

    const int qrA = q0 + w * 16 + (lane >> 2);
    const int qrB = qrA + 8;
    if (k0 + ABN - 1 > q0) {   // causal mask
      #pragma unroll
      for (int nt = 0; nt < 8; ++nt) {
        const int kc = k0 + nt * 8 + ((lane & 3) << 1);
        if (kc     > qrA) sacc[nt][0] = -1e30f;
        if (kc + 1 > qrA) sacc[nt][1] = -1e30f;
        if (kc     > qrB) sacc[nt][2] = -1e30f;
        if (kc + 1 > qrB) sacc[nt][3] = -1e30f;
      }
    }

    // ---- online softmax (base-2) ----
    float mxA = -1e30f, mxB = -1e30f;
    #pragma unroll
    for (int nt = 0; nt < 8; ++nt) {
      mxA = fmaxf(mxA, fmaxf(sacc[nt][0], sacc[nt][1]));
      mxB = fmaxf(mxB, fmaxf(sacc[nt][2], sacc[nt][3]));
    }
    mxA = fmaxf(mxA, __shfl_xor_sync(0xffffffffu, mxA, 1));
    mxA = fmaxf(mxA, __shfl_xor_sync(0xffffffffu, mxA, 2));
    mxB = fmaxf(mxB, __shfl_xor_sync(0xffffffffu, mxB, 1));
    mxB = fmaxf(mxB, __shfl_xor_sync(0xffffffffu, mxB, 2));
    const float mnA = fmaxf(mA, mxA), mnB = fmaxf(mB, mxB);
    const float cA = exp2f(mA - mnA), cB = exp2f(mB - mnB);
    mA = mnA; mB = mnB;

    float rsA = 0.f, rsB = 0.f;
    #pragma unroll
    for (int nt = 0; nt < 8; ++nt) {
      sacc[nt][0] = exp2f(sacc[nt][0] - mnA);
      sacc[nt][1] = exp2f(sacc[nt][1] - mnA);
      sacc[nt][2] = exp2f(sacc[nt][2] - mnB);
      sacc[nt][3] = exp2f(sacc[nt][3] - mnB);
      rsA += sacc[nt][0] + sacc[nt][1];
      rsB += sacc[nt][2] + sacc[nt][3];
    }
    rsA += __shfl_xor_sync(0xffffffffu, rsA, 1);
    rsA += __shfl_xor_sync(0xffffffffu, rsA, 2);
    rsB += __shfl_xor_sync(0xffffffffu, rsB, 1);
    rsB += __shfl_xor_sync(0xffffffffu, rsB, 2);
    lA = lA * cA + rsA;
    lB = lB * cB + rsB;
    #pragma unroll
    for (int nt = 0; nt < 16; ++nt) {
      oacc[nt][0] *= cA; oacc[nt][1] *= cA;
      oacc[nt][2] *= cB; oacc[nt][3] *= cB;
    }

    // ---- O += P @ V (fp16 1-term) ----
    #pragma unroll
    for (int kk = 0; kk < 4; ++kk) {
      uint32_t ph[4];
      __half2 p0 = __floats2half2_rn(sacc[2*kk][0],   sacc[2*kk][1]);
      __half2 p1 = __floats2half2_rn(sacc[2*kk][2],   sacc[2*kk][3]);
      __half2 p2 = __floats2half2_rn(sacc[2*kk+1][0], sacc[2*kk+1][1]);
      __half2 p3 = __floats2half2_rn(sacc[2*kk+1][2], sacc[2*kk+1][3]);
      ph[0] = *reinterpret_cast<uint32_t*>(&p0);
      ph[1] = *reinterpret_cast<uint32_t*>(&p1);
      ph[2] = *reinterpret_cast<uint32_t*>(&p2);
      ph[3] = *reinterpret_cast<uint32_t*>(&p3);
      #pragma unroll
      for (int np = 0; np < 8; ++np) {
        uint32_t vf[4];
        const uint32_t va = stb + (uint32_t)((FV + (np * 16 + b_r) * VTP +
                                              kk * 16 + b_k) << 1);
        LDSM4(vf, va);
        MMA_F16(oacc[2*np],   ph, (&vf[0]));
        MMA_F16(oacc[2*np+1], ph, (&vf[2]));
      }
    }

    __syncthreads();
    if (kt + 2 <= ktmax) LOADKV(kt + 2);
  }

  // ---- epilogue: write fp16 (GEMM2 A operand) ----
  const float invA = 1.0f / lA, invB = 1.0f / lB;
  const int rowA = q0 + w * 16 + (lane >> 2);
  #pragma unroll
  for (int nt = 0; nt < 16; ++nt) {
    const int c0 = h * HD + nt * 8 + ((lane & 3) << 1);
    __half2 pa = __floats2half2_rn(oacc[nt][0] * invA, oacc[nt][1] * invA);
    __half2 pb = __floats2half2_rn(oacc[nt][2] * invB, oacc[nt][3] * invB);
    *(__half2*)&ob[(size_t)rowA * ON + c0]       = pa;
    *(__half2*)&ob[(size_t)(rowA + 8) * ON + c0] = pb;
  }
}

// ---------------------------------------------------------------------------
extern "C" void kernel_launch(void* const* d_in, const int* in_sizes, int n_in,
                              void* d_out, int out_size)
{
  (void)in_sizes; (void)n_in; (void)out_size;
  const int*   positions = (const int*)  d_in[0];
  const float* hidden    = (const float*)d_in[1];
  const float* w_qkv     = (const float*)d_in[2];
  const float* w_o       = (const float*)d_in[3];
  const float* qw        = (const float*)d_in[4];
  const float* kw        = (const float*)d_in[5];
  float* out = (float*)d_out;

  float* qkv;
  cudaGetSymbolAddress((void**)&qkv, g_qkv);
  __half *hid_h, *wqkv_h, *wo_h, *ob, *vt, *qf, *kf;
  float2* rope;
  cudaGetSymbolAddress((void**)&hid_h,  g_hid_h);
  cudaGetSymbolAddress((void**)&wqkv_h, g_wqkv_h);
  cudaGetSymbolAddress((void**)&wo_h,   g_wo_h);
  cudaGetSymbolAddress((void**)&ob,     g_ob);
  cudaGetSymbolAddress((void**)&vt,     g_vt);
  cudaGetSymbolAddress((void**)&qf,     g_q);
  cudaGetSymbolAddress((void**)&kf,     g_k);
  cudaGetSymbolAddress((void**)&rope,   g_rope);

  cudaFuncSetAttribute(gemm_mma, cudaFuncAttributeMaxDynamicSharedMemorySize,
                       GEMM_SMEM);
  cudaFuncSetAttribute(flash_mma, cudaFuncAttributeMaxDynamicSharedMemorySize,
                       FLASH_SMEM);

  // 0) fp32 -> fp16 operand converts for GEMM1 + rope table
  {
    int n4 = T_TOK * HIDN / 4;
    cvt_f16<<<(n4 + 255) / 256, 256>>>(hidden, hid_h, n4);
    n4 = QKV_N * HIDN / 4;
    cvt_f16<<<(n4 + 255) / 256, 256>>>(w_qkv, wqkv_h, n4);
    rope_table<<<(T_TOK * 64) / 256, 256>>>(positions, rope);
  }

  // 1) QKV projection (fp16 single-term HMMA)
  gemm_mma<<<dim3(QKV_N/128, T_TOK/128), 512, GEMM_SMEM>>>(
      hid_h, wqkv_h, qkv, T_TOK, QKV_N, HIDN);

  // 2) RMSNorm + RoPE (table) -> Q/K fp16 ; V transpose (fp16)
  norm_rope<<<dim3(T_TOK, NH + NKV), 128>>>(qkv, rope, qw, kw, qf, kf);
  vtrans<<<dim3(T_TOK/64, NKV), 256>>>(qkv, vt);

  // 3) Causal GQA flash attention (fp16, exp2 softmax, 1 CTA/SM, LPT)
  flash_mma<<<dim3(T_TOK/ABM, NH), 256, FLASH_SMEM>>>(qf, kf, vt, ob);

  // 4) fp32 -> fp16 convert for w_o
  {
    int n4 = HIDN * ON / 4;
    cvt_f16<<<(n4 + 255) / 256, 256>>>(w_o, wo_h, n4);
  }

  // 5) Output projection (fp16 single-term HMMA)
  gemm_mma<<<dim3(HIDN/128, T_TOK/128), 512, GEMM_SMEM>>>(
      ob, wo_h, out, T_TOK, HIDN, ON);
}